// round 7
// baseline (speedup 1.0000x reference)
#include <cuda_runtime.h>
#include <cuda_fp16.h>
#include <math.h>
#include <stdint.h>

#define B_    4
#define L_    4096
#define D_    1024
#define DFF_  4096
#define KCAP_ 2048
#define UNSEL_ 2048

// ------------------------- scratch globals -------------------------
__device__ float g_scores[B_ * L_];
__device__ int   g_flags[B_ * L_];
__device__ int   g_selidx[B_ * KCAP_];
__device__ int   g_unselidx[B_ * UNSEL_];

__device__ __align__(16) __half g_xg16[(size_t)B_ * KCAP_ * D_];
__device__ __align__(16) __half g_xu16[(size_t)B_ * UNSEL_ * D_];
__device__ __align__(16) __half g_wb16[(size_t)D_ * D_];
__device__ __align__(16) __half g_w116[(size_t)DFF_ * D_];
__device__ __align__(16) __half g_w216[(size_t)D_ * DFF_];
__device__ __align__(16) __half g_h16 [(size_t)B_ * KCAP_ * DFF_];

// ------------------------- helpers -------------------------
__device__ __forceinline__ uint32_t smem_u32(const void* p) {
    uint32_t a;
    asm("{ .reg .u64 t; cvta.to.shared.u64 t, %1; cvt.u32.u64 %0, t; }"
        : "=r"(a) : "l"(p));
    return a;
}
__device__ __forceinline__ void cp16(uint32_t dst, const void* src) {
    asm volatile("cp.async.cg.shared.global [%0], [%1], 16;" :: "r"(dst), "l"(src));
}
#define CP_COMMIT() asm volatile("cp.async.commit_group;" ::: "memory")
#define CP_WAIT1()  asm volatile("cp.async.wait_group 1;" ::: "memory")

__device__ __forceinline__ void ldx4(uint32_t r[4], uint32_t addr) {
    asm volatile("ldmatrix.sync.aligned.m8n8.x4.shared.b16 {%0,%1,%2,%3}, [%4];"
                 : "=r"(r[0]), "=r"(r[1]), "=r"(r[2]), "=r"(r[3]) : "r"(addr));
}
__device__ __forceinline__ void mma16816(float c[4], const uint32_t a[4], const uint32_t b[2]) {
    asm volatile(
        "mma.sync.aligned.m16n8k16.row.col.f32.f16.f16.f32 "
        "{%0,%1,%2,%3}, {%4,%5,%6,%7}, {%8,%9}, {%0,%1,%2,%3};"
        : "+f"(c[0]), "+f"(c[1]), "+f"(c[2]), "+f"(c[3])
        : "r"(a[0]), "r"(a[1]), "r"(a[2]), "r"(a[3]), "r"(b[0]), "r"(b[1]));
}
__device__ __forceinline__ float gelu_tanh(float v) {
    const float c = 0.7978845608028654f;
    float u = c * (v + 0.044715f * v * v * v);
    return 0.5f * v * (1.0f + tanhf(u));
}

// ------------------------- router / top-k / compact -------------------------
__global__ void router_scores_kernel(const float* __restrict__ x,
                                     const float* __restrict__ wr) {
    int gwarp = (blockIdx.x * blockDim.x + threadIdx.x) >> 5;
    int lane  = threadIdx.x & 31;
    if (gwarp >= B_ * L_) return;
    const float4* xr = (const float4*)(x + (size_t)gwarp * D_);
    const float4* w4 = (const float4*)wr;
    float acc = 0.f;
#pragma unroll
    for (int i = 0; i < D_ / 4 / 32; i++) {
        float4 a = xr[lane + i * 32];
        float4 b = w4[lane + i * 32];
        acc += a.x * b.x + a.y * b.y + a.z * b.z + a.w * b.w;
    }
#pragma unroll
    for (int off = 16; off; off >>= 1)
        acc += __shfl_xor_sync(0xffffffffu, acc, off);
    if (lane == 0) g_scores[gwarp] = acc;
}

__global__ void rank_kernel() {
    __shared__ float s[L_];
    int b = blockIdx.y;
    int t = threadIdx.x;
    const float* sc = g_scores + b * L_;
    for (int i = t; i < L_; i += 1024) s[i] = sc[i];
    __syncthreads();
    int   l  = blockIdx.x * 1024 + t;
    float sl = s[l];
    int rank = 0;
#pragma unroll 8
    for (int j = 0; j < L_; j++) {
        float sj = s[j];
        rank += (sj > sl) || (sj == sl && j < l);
    }
    g_flags[b * L_ + l] = (rank < KCAP_) ? 1 : 0;
}

__global__ void compact_kernel() {
    int b = blockIdx.x;
    int t = threadIdx.x;
    int tok0 = t * 4;
    int f[4], c = 0;
#pragma unroll
    for (int i = 0; i < 4; i++) {
        f[i] = g_flags[b * L_ + tok0 + i];
        c += f[i];
    }
    int lane = t & 31, w = t >> 5;
    int inc = c;
#pragma unroll
    for (int off = 1; off < 32; off <<= 1) {
        int y = __shfl_up_sync(0xffffffffu, inc, off);
        if (lane >= off) inc += y;
    }
    __shared__ int ws[32];
    if (lane == 31) ws[w] = inc;
    __syncthreads();
    if (w == 0) {
        int v = ws[lane];
#pragma unroll
        for (int off = 1; off < 32; off <<= 1) {
            int y = __shfl_up_sync(0xffffffffu, v, off);
            if (lane >= off) v += y;
        }
        ws[lane] = v;
    }
    __syncthreads();
    int selp = inc - c + (w ? ws[w - 1] : 0);
    int unsp = tok0 - selp;
#pragma unroll
    for (int i = 0; i < 4; i++) {
        if (f[i]) g_selidx[b * KCAP_ + selp++] = tok0 + i;
        else      g_unselidx[b * UNSEL_ + unsp++] = tok0 + i;
    }
}

// ------------------------- conversions -------------------------
__global__ void convert16_kernel(const float* __restrict__ src,
                                 __half* __restrict__ dst, int n4) {
    int i = blockIdx.x * blockDim.x + threadIdx.x;
    if (i >= n4) return;
    float4 v = ((const float4*)src)[i];
    __half2 a = __floats2half2_rn(v.x, v.y);
    __half2 b = __floats2half2_rn(v.z, v.w);
    ((uint2*)dst)[i] = make_uint2(*(uint32_t*)&a, *(uint32_t*)&b);
}

__global__ void gather_convert16_kernel(const float* __restrict__ x,
                                        const int* __restrict__ idx,
                                        __half* __restrict__ dst) {
    int i = blockIdx.x * blockDim.x + threadIdx.x;   // rows * 256
    int r = i >> 8;
    int c4 = i & 255;
    int srow = (r >> 11) * L_ + idx[r];
    float4 v = ((const float4*)(x + (size_t)srow * D_))[c4];
    __half2 a = __floats2half2_rn(v.x, v.y);
    __half2 b = __floats2half2_rn(v.z, v.w);
    ((uint2*)dst)[i] = make_uint2(*(uint32_t*)&a, *(uint32_t*)&b);
}

// ------------------------- HMMA GEMM core -------------------------
// 128x128 CTA tile, 128 threads, 4 warps of 64x64. K-chunk 64.
// smem tile: 128 rows x 128B (64 halves), swizzle: 16B chunk c of row r at c^(r&7)
#define TILEB   16384
#define STAGEB  (2 * TILEB)        // A tile + B tile
#define NSTAGE  3
#define SMEMB   (NSTAGE * STAGEB)  // 98304
#define BKC     64

#define SWZ128(r, c) (((uint32_t)(r)) * 128u + ((((uint32_t)(c)) ^ (((uint32_t)(r)) & 7u)) << 4))

// FUSED==1: tiles [0,512) bypass (A=xu,B=wb, scatter unsel, 64x8 tiles),
//           tiles [512,2560) ffn1 (A=xg,B=w1, gelu->h16, 64x32 tiles). K=1024.
// FUSED==0: ffn2 (A=h16,B=w2, scatter sel, 64x8 tiles). K=4096.
template <int FUSED>
__global__ void __launch_bounds__(128, 2) gemm_mma(float* __restrict__ outp) {
    constexpr int K  = FUSED ? D_ : DFF_;
    constexpr int NK = K / BKC;
    constexpr int NTILES = FUSED ? (512 + 2048) : 512;

    extern __shared__ char smem[];
    const uint32_t sbase = smem_u32(smem);

    const int tid  = threadIdx.x;
    const int lane = tid & 31;
    const int wid  = tid >> 5;

    // cp.async: thread owns one row (pr = tid), 8 x 16B chunks per tile
    const int pr = tid;
    uint32_t dsw[8];
#pragma unroll
    for (int c = 0; c < 8; c++) dsw[c] = SWZ128(pr, c);

    // warp tiling: 2(m) x 2(n), warp tile 64x64
    const uint32_t wrow0 = (wid & 1) * 64;
    const uint32_t wcol0 = (wid >> 1) * 64;
    const uint32_t aRow = wrow0 + (lane & 15);
    const uint32_t aK   = (lane >> 4);
    const uint32_t bRow = wcol0 + ((lane >> 4) << 3) + (lane & 7);
    const uint32_t bK   = (lane >> 3) & 1;

    uint32_t aBase[4], aSwz[4];
#pragma unroll
    for (int i = 0; i < 4; i++) {
        uint32_t r = aRow + i * 16;
        aBase[i] = r * 128u;
        aSwz[i]  = r & 7u;
    }
    uint32_t bBase[4], bSwz[4];
#pragma unroll
    for (int jp = 0; jp < 4; jp++) {
        uint32_t r = bRow + jp * 16;
        bBase[jp] = r * 128u;
        bSwz[jp]  = r & 7u;
    }

    const int t4  = lane >> 2;
    const int tm2 = (lane & 3) * 2;

    for (int tile = blockIdx.x; tile < NTILES; tile += gridDim.x) {
        int bm, bn;
        const __half* A;
        const __half* B;
        bool ffn1;
        if (FUSED) {
            ffn1 = (tile >= 512);
            if (ffn1) { int t = tile - 512; bm = t >> 5; bn = t & 31; A = g_xg16; B = g_w116; }
            else      { bm = tile >> 3; bn = tile & 7;   A = g_xu16; B = g_wb16; }
        } else {
            ffn1 = false;
            bm = tile >> 3; bn = tile & 7;
            A = g_h16; B = g_w216;
        }

        const __half* srcA = A + (size_t)(bm * 128 + pr) * K;
        const __half* srcB = B + (size_t)(bn * 128 + pr) * K;

#define LOAD_STAGE(ks, st) do {                                          \
        uint32_t b0 = sbase + (st) * STAGEB;                             \
        int ko = (ks) * BKC;                                             \
        _Pragma("unroll")                                                \
        for (int c = 0; c < 8; c++) {                                    \
            cp16(b0 + dsw[c],         srcA + ko + c * 8);                \
            cp16(b0 + TILEB + dsw[c], srcB + ko + c * 8);                \
        }                                                                \
        CP_COMMIT();                                                     \
    } while (0)

        float acc[4][8][4];
#pragma unroll
        for (int i = 0; i < 4; i++)
#pragma unroll
            for (int j = 0; j < 8; j++)
#pragma unroll
                for (int q = 0; q < 4; q++) acc[i][j][q] = 0.f;

        // make sure no warp still reads last tile's smem before overwriting
        __syncthreads();

        LOAD_STAGE(0, 0);
        LOAD_STAGE(1, 1);

        int st = 0;
        for (int ks = 0; ks < NK; ks++) {
            CP_WAIT1();
            __syncthreads();

            if (ks + 2 < NK) {
                int st2 = st + 2; if (st2 >= NSTAGE) st2 -= NSTAGE;
                LOAD_STAGE(ks + 2, st2);
            } else {
                CP_COMMIT();
            }

            const uint32_t base = sbase + st * STAGEB;
#pragma unroll
            for (int s = 0; s < 4; s++) {
                uint32_t a[4][4];
                uint32_t b[8][2];
                const uint32_t cA = 2 * s + aK;
                const uint32_t cB = 2 * s + bK;
#pragma unroll
                for (int i = 0; i < 4; i++)
                    ldx4(a[i], base + aBase[i] + (((cA ^ aSwz[i]) & 7u) << 4));
#pragma unroll
                for (int jp = 0; jp < 4; jp++) {
                    uint32_t r[4];
                    ldx4(r, base + TILEB + bBase[jp] + (((cB ^ bSwz[jp]) & 7u) << 4));
                    b[2 * jp][0] = r[0]; b[2 * jp][1] = r[1];
                    b[2 * jp + 1][0] = r[2]; b[2 * jp + 1][1] = r[3];
                }
#pragma unroll
                for (int i = 0; i < 4; i++)
#pragma unroll
                    for (int j = 0; j < 8; j++) mma16816(acc[i][j], a[i], b[j]);
            }
            if (++st == NSTAGE) st = 0;
        }

        // ---- epilogue ----
#pragma unroll
        for (int i = 0; i < 4; i++) {
            int r0 = bm * 128 + (int)wrow0 + i * 16 + t4;
            int r1 = r0 + 8;
            int or0, or1;
            if (FUSED) {
                if (ffn1) { or0 = r0; or1 = r1; }
                else { or0 = (r0 >> 11) * L_ + g_unselidx[r0]; or1 = (r1 >> 11) * L_ + g_unselidx[r1]; }
            } else {
                or0 = (r0 >> 11) * L_ + g_selidx[r0];
                or1 = (r1 >> 11) * L_ + g_selidx[r1];
            }
#pragma unroll
            for (int j = 0; j < 8; j++) {
                int col = bn * 128 + (int)wcol0 + j * 8 + tm2;
                if (FUSED && ffn1) {
                    __half2 p0 = __floats2half2_rn(gelu_tanh(acc[i][j][0]), gelu_tanh(acc[i][j][1]));
                    __half2 p1 = __floats2half2_rn(gelu_tanh(acc[i][j][2]), gelu_tanh(acc[i][j][3]));
                    *(uint32_t*)(g_h16 + (size_t)r0 * DFF_ + col) = *(uint32_t*)&p0;
                    *(uint32_t*)(g_h16 + (size_t)r1 * DFF_ + col) = *(uint32_t*)&p1;
                } else {
                    *(float2*)(outp + (size_t)or0 * D_ + col) = make_float2(acc[i][j][0], acc[i][j][1]);
                    *(float2*)(outp + (size_t)or1 * D_ + col) = make_float2(acc[i][j][2], acc[i][j][3]);
                }
            }
        }
#undef LOAD_STAGE
    }
}

// ------------------------- launch -------------------------
extern "C" void kernel_launch(void* const* d_in, const int* in_sizes, int n_in,
                              void* d_out, int out_size) {
    const float* x  = (const float*)d_in[0];
    const float* wr = (const float*)d_in[1];
    const float* wb = (const float*)d_in[2];
    const float* w1 = (const float*)d_in[3];
    const float* w2 = (const float*)d_in[4];
    float* out = (float*)d_out;

    cudaFuncSetAttribute(gemm_mma<1>, cudaFuncAttributeMaxDynamicSharedMemorySize, SMEMB);
    cudaFuncSetAttribute(gemm_mma<0>, cudaFuncAttributeMaxDynamicSharedMemorySize, SMEMB);

    router_scores_kernel<<<(B_ * L_) / 8, 256>>>(x, wr);
    rank_kernel<<<dim3(L_ / 1024, B_), 1024>>>();
    compact_kernel<<<B_, 1024>>>();

    __half *p_wb, *p_w1, *p_w2, *p_xg, *p_xu;
    int *p_sel, *p_unsel;
    cudaGetSymbolAddress((void**)&p_wb, g_wb16);
    cudaGetSymbolAddress((void**)&p_w1, g_w116);
    cudaGetSymbolAddress((void**)&p_w2, g_w216);
    cudaGetSymbolAddress((void**)&p_xg, g_xg16);
    cudaGetSymbolAddress((void**)&p_xu, g_xu16);
    cudaGetSymbolAddress((void**)&p_sel, g_selidx);
    cudaGetSymbolAddress((void**)&p_unsel, g_unselidx);

    convert16_kernel<<<(D_ * D_ / 4) / 256, 256>>>(wb, p_wb, D_ * D_ / 4);
    convert16_kernel<<<(DFF_ * D_ / 4) / 256, 256>>>(w1, p_w1, DFF_ * D_ / 4);
    convert16_kernel<<<(D_ * DFF_ / 4) / 256, 256>>>(w2, p_w2, D_ * DFF_ / 4);
    gather_convert16_kernel<<<(B_ * KCAP_  * 256) / 256, 256>>>(x, p_sel,   p_xg);
    gather_convert16_kernel<<<(B_ * UNSEL_ * 256) / 256, 256>>>(x, p_unsel, p_xu);

    // persistent GEMMs: 2 CTAs/SM x 148 SMs
    gemm_mma<1><<<296, 128, SMEMB>>>(out);   // bypass + ffn1 fused
    gemm_mma<0><<<296, 128, SMEMB>>>(out);   // ffn2 scatter
}

// round 8
// speedup vs baseline: 1.3753x; 1.3753x over previous
#include <cuda_runtime.h>
#include <cuda_fp16.h>
#include <math.h>
#include <stdint.h>

#define B_    4
#define L_    4096
#define D_    1024
#define DFF_  4096
#define KCAP_ 2048
#define UNSEL_ 2048

// ------------------------- scratch globals -------------------------
__device__ float g_scores[B_ * L_];
__device__ int   g_flags[B_ * L_];
__device__ int   g_selidx[B_ * KCAP_];
__device__ int   g_unselidx[B_ * UNSEL_];

__device__ __align__(16) __half g_xg16[(size_t)B_ * KCAP_ * D_];
__device__ __align__(16) __half g_xu16[(size_t)B_ * UNSEL_ * D_];
__device__ __align__(16) __half g_wb16[(size_t)D_ * D_];
__device__ __align__(16) __half g_w116[(size_t)DFF_ * D_];
__device__ __align__(16) __half g_w216[(size_t)D_ * DFF_];
__device__ __align__(16) __half g_h16 [(size_t)B_ * KCAP_ * DFF_];

// ------------------------- helpers -------------------------
__device__ __forceinline__ uint32_t smem_u32(const void* p) {
    uint32_t a;
    asm("{ .reg .u64 t; cvta.to.shared.u64 t, %1; cvt.u32.u64 %0, t; }"
        : "=r"(a) : "l"(p));
    return a;
}
__device__ __forceinline__ void cp16(uint32_t dst, const void* src) {
    asm volatile("cp.async.cg.shared.global [%0], [%1], 16;" :: "r"(dst), "l"(src));
}
#define CP_COMMIT() asm volatile("cp.async.commit_group;" ::: "memory")
#define CP_WAIT3()  asm volatile("cp.async.wait_group 3;" ::: "memory")

__device__ __forceinline__ void ldx4(uint32_t r[4], uint32_t addr) {
    asm volatile("ldmatrix.sync.aligned.m8n8.x4.shared.b16 {%0,%1,%2,%3}, [%4];"
                 : "=r"(r[0]), "=r"(r[1]), "=r"(r[2]), "=r"(r[3]) : "r"(addr));
}
__device__ __forceinline__ void mma16816(float c[4], const uint32_t a[4], const uint32_t b[2]) {
    asm volatile(
        "mma.sync.aligned.m16n8k16.row.col.f32.f16.f16.f32 "
        "{%0,%1,%2,%3}, {%4,%5,%6,%7}, {%8,%9}, {%0,%1,%2,%3};"
        : "+f"(c[0]), "+f"(c[1]), "+f"(c[2]), "+f"(c[3])
        : "r"(a[0]), "r"(a[1]), "r"(a[2]), "r"(a[3]), "r"(b[0]), "r"(b[1]));
}
__device__ __forceinline__ float gelu_tanh(float v) {
    const float c = 0.7978845608028654f;
    float u = c * (v + 0.044715f * v * v * v);
    return 0.5f * v * (1.0f + tanhf(u));
}

// ------------------------- router / top-k / compact -------------------------
__global__ void router_scores_kernel(const float* __restrict__ x,
                                     const float* __restrict__ wr) {
    int gwarp = (blockIdx.x * blockDim.x + threadIdx.x) >> 5;
    int lane  = threadIdx.x & 31;
    if (gwarp >= B_ * L_) return;
    const float4* xr = (const float4*)(x + (size_t)gwarp * D_);
    const float4* w4 = (const float4*)wr;
    float acc = 0.f;
#pragma unroll
    for (int i = 0; i < D_ / 4 / 32; i++) {
        float4 a = xr[lane + i * 32];
        float4 b = w4[lane + i * 32];
        acc += a.x * b.x + a.y * b.y + a.z * b.z + a.w * b.w;
    }
#pragma unroll
    for (int off = 16; off; off >>= 1)
        acc += __shfl_xor_sync(0xffffffffu, acc, off);
    if (lane == 0) g_scores[gwarp] = acc;
}

__global__ void rank_kernel() {
    __shared__ float s[L_];
    int b = blockIdx.y;
    int t = threadIdx.x;
    const float* sc = g_scores + b * L_;
    for (int i = t; i < L_; i += 1024) s[i] = sc[i];
    __syncthreads();
    int   l  = blockIdx.x * 1024 + t;
    float sl = s[l];
    int rank = 0;
#pragma unroll 8
    for (int j = 0; j < L_; j++) {
        float sj = s[j];
        rank += (sj > sl) || (sj == sl && j < l);
    }
    g_flags[b * L_ + l] = (rank < KCAP_) ? 1 : 0;
}

__global__ void compact_kernel() {
    int b = blockIdx.x;
    int t = threadIdx.x;
    int tok0 = t * 4;
    int f[4], c = 0;
#pragma unroll
    for (int i = 0; i < 4; i++) {
        f[i] = g_flags[b * L_ + tok0 + i];
        c += f[i];
    }
    int lane = t & 31, w = t >> 5;
    int inc = c;
#pragma unroll
    for (int off = 1; off < 32; off <<= 1) {
        int y = __shfl_up_sync(0xffffffffu, inc, off);
        if (lane >= off) inc += y;
    }
    __shared__ int ws[32];
    if (lane == 31) ws[w] = inc;
    __syncthreads();
    if (w == 0) {
        int v = ws[lane];
#pragma unroll
        for (int off = 1; off < 32; off <<= 1) {
            int y = __shfl_up_sync(0xffffffffu, v, off);
            if (lane >= off) v += y;
        }
        ws[lane] = v;
    }
    __syncthreads();
    int selp = inc - c + (w ? ws[w - 1] : 0);
    int unsp = tok0 - selp;
#pragma unroll
    for (int i = 0; i < 4; i++) {
        if (f[i]) g_selidx[b * KCAP_ + selp++] = tok0 + i;
        else      g_unselidx[b * UNSEL_ + unsp++] = tok0 + i;
    }
}

// ------------------------- conversions -------------------------
__global__ void convert16_kernel(const float* __restrict__ src,
                                 __half* __restrict__ dst, int n4) {
    int i = blockIdx.x * blockDim.x + threadIdx.x;
    if (i >= n4) return;
    float4 v = ((const float4*)src)[i];
    __half2 a = __floats2half2_rn(v.x, v.y);
    __half2 b = __floats2half2_rn(v.z, v.w);
    ((uint2*)dst)[i] = make_uint2(*(uint32_t*)&a, *(uint32_t*)&b);
}

__global__ void gather_convert16_kernel(const float* __restrict__ x,
                                        const int* __restrict__ idx,
                                        __half* __restrict__ dst) {
    int i = blockIdx.x * blockDim.x + threadIdx.x;   // rows * 256
    int r = i >> 8;
    int c4 = i & 255;
    int srow = (r >> 11) * L_ + idx[r];
    float4 v = ((const float4*)(x + (size_t)srow * D_))[c4];
    __half2 a = __floats2half2_rn(v.x, v.y);
    __half2 b = __floats2half2_rn(v.z, v.w);
    ((uint2*)dst)[i] = make_uint2(*(uint32_t*)&a, *(uint32_t*)&b);
}

// ------------------------- HMMA GEMM (fp16 single-pass, round-5 core) ----------
// 128x128 CTA tile, 256 threads, 8 warps of 64x32. K-chunk 32, 5 stages.
// smem tile: 128 rows x 64B, swizzle: 16B chunk c of row r at c ^ ((r>>1)&3)
#define BKC     32
#define TILEB   8192               // 128 rows x 64B (swizzled)
#define STAGEB  (2 * TILEB)        // A, B
#define NSTAGE  5
#define SMEMB   (NSTAGE * STAGEB)  // 81920

#define SWZ(r, c) (((uint32_t)(r)) * 64u + ((((uint32_t)(c)) ^ ((((uint32_t)(r)) >> 1) & 3u)) << 4))

// FUSED==1: tiles [0,512) bypass (A=xu,B=wb, scatter unsel, 64x8),
//           tiles [512,2560) ffn1 (A=xg,B=w1, gelu->h16, 64x32). K=1024.
// FUSED==0: ffn2 (A=h16,B=w2, scatter sel, 64x8). K=4096.
template <int FUSED>
__global__ void __launch_bounds__(256, 2) gemm_mma(float* __restrict__ outp) {
    constexpr int K  = FUSED ? D_ : DFF_;
    constexpr int NK = K / BKC;
    constexpr int NTILES = FUSED ? (512 + 2048) : 512;

    extern __shared__ char smem[];
    const uint32_t sbase = smem_u32(smem);

    const int tid  = threadIdx.x;
    const int lane = tid & 31;
    const int wid  = tid >> 5;

    // cp.async per-thread layout: row pr, chunk pair pc{,+1}
    const int pr = tid >> 1;
    const int pc = (tid & 1) * 2;
    const uint32_t d0 = SWZ(pr, pc);
    const uint32_t d1 = SWZ(pr, pc + 1);

    // warp tiling: 2(m) x 4(n), warp tile 64x32
    const uint32_t wrow0 = (wid & 1) * 64;
    const uint32_t wcol0 = (wid >> 1) * 32;
    const uint32_t aRow = wrow0 + (lane & 15);
    const uint32_t aK   = (lane >> 4);
    const uint32_t bRow = wcol0 + ((lane >> 4) << 3) + (lane & 7);
    const uint32_t bK   = (lane >> 3) & 1;

    uint32_t aBase[4], aSwz[4];
#pragma unroll
    for (int i = 0; i < 4; i++) {
        uint32_t r = aRow + i * 16;
        aBase[i] = r * 64u;
        aSwz[i]  = (r >> 1) & 3u;
    }
    uint32_t bBase[2], bSwz[2];
#pragma unroll
    for (int jp = 0; jp < 2; jp++) {
        uint32_t r = bRow + jp * 16;
        bBase[jp] = r * 64u;
        bSwz[jp]  = (r >> 1) & 3u;
    }

    const int t4  = lane >> 2;
    const int tm2 = (lane & 3) * 2;

    for (int tile = blockIdx.x; tile < NTILES; tile += gridDim.x) {
        int bm, bn;
        const __half* A;
        const __half* B;
        bool ffn1;
        if (FUSED) {
            ffn1 = (tile >= 512);
            if (ffn1) { int t = tile - 512; bm = t >> 5; bn = t & 31; A = g_xg16; B = g_w116; }
            else      { bm = tile >> 3; bn = tile & 7;   A = g_xu16; B = g_wb16; }
        } else {
            ffn1 = false;
            bm = tile >> 3; bn = tile & 7;
            A = g_h16; B = g_w216;
        }

        const __half* srcA = A + (size_t)(bm * 128 + pr) * K + pc * 8;
        const __half* srcB = B + (size_t)(bn * 128 + pr) * K + pc * 8;

#define LOAD_STAGE(ks, st) do {                                          \
        uint32_t b0 = sbase + (st) * STAGEB;                             \
        int ko = (ks) * BKC;                                             \
        cp16(b0 + d0,         srcA + ko);                                \
        cp16(b0 + d1,         srcA + ko + 8);                            \
        cp16(b0 + TILEB + d0, srcB + ko);                                \
        cp16(b0 + TILEB + d1, srcB + ko + 8);                            \
        CP_COMMIT();                                                     \
    } while (0)

        float acc[4][4][4];
#pragma unroll
        for (int i = 0; i < 4; i++)
#pragma unroll
            for (int j = 0; j < 4; j++)
#pragma unroll
                for (int q = 0; q < 4; q++) acc[i][j][q] = 0.f;

        // no warp may still read the previous tile's smem when we overwrite
        __syncthreads();

        LOAD_STAGE(0, 0);
        LOAD_STAGE(1, 1);
        LOAD_STAGE(2, 2);
        LOAD_STAGE(3, 3);

        int st = 0;
        for (int ks = 0; ks < NK; ks++) {
            CP_WAIT3();
            __syncthreads();

            if (ks + 4 < NK) {
                int st4 = st + 4; if (st4 >= NSTAGE) st4 -= NSTAGE;
                LOAD_STAGE(ks + 4, st4);
            } else {
                CP_COMMIT();
            }

            const uint32_t base = sbase + st * STAGEB;
#pragma unroll
            for (int s = 0; s < 2; s++) {
                uint32_t a[4][4];
                uint32_t b[4][2];
#pragma unroll
                for (int i = 0; i < 4; i++) {
                    uint32_t c = 2 * s + aK;
                    ldx4(a[i], base + aBase[i] + ((c ^ aSwz[i]) << 4));
                }
#pragma unroll
                for (int jp = 0; jp < 2; jp++) {
                    uint32_t r[4];
                    uint32_t c = 2 * s + bK;
                    ldx4(r, base + TILEB + bBase[jp] + ((c ^ bSwz[jp]) << 4));
                    b[2 * jp][0] = r[0]; b[2 * jp][1] = r[1];
                    b[2 * jp + 1][0] = r[2]; b[2 * jp + 1][1] = r[3];
                }
#pragma unroll
                for (int i = 0; i < 4; i++)
#pragma unroll
                    for (int j = 0; j < 4; j++) mma16816(acc[i][j], a[i], b[j]);
            }
            if (++st == NSTAGE) st = 0;
        }

        // ---- epilogue ----
#pragma unroll
        for (int i = 0; i < 4; i++) {
            int r0 = bm * 128 + (int)wrow0 + i * 16 + t4;
            int r1 = r0 + 8;
            int or0, or1;
            if (FUSED) {
                if (ffn1) { or0 = r0; or1 = r1; }
                else { or0 = (r0 >> 11) * L_ + g_unselidx[r0]; or1 = (r1 >> 11) * L_ + g_unselidx[r1]; }
            } else {
                or0 = (r0 >> 11) * L_ + g_selidx[r0];
                or1 = (r1 >> 11) * L_ + g_selidx[r1];
            }
#pragma unroll
            for (int j = 0; j < 4; j++) {
                int col = bn * 128 + (int)wcol0 + j * 8 + tm2;
                if (FUSED && ffn1) {
                    __half2 p0 = __floats2half2_rn(gelu_tanh(acc[i][j][0]), gelu_tanh(acc[i][j][1]));
                    __half2 p1 = __floats2half2_rn(gelu_tanh(acc[i][j][2]), gelu_tanh(acc[i][j][3]));
                    *(uint32_t*)(g_h16 + (size_t)r0 * DFF_ + col) = *(uint32_t*)&p0;
                    *(uint32_t*)(g_h16 + (size_t)r1 * DFF_ + col) = *(uint32_t*)&p1;
                } else {
                    *(float2*)(outp + (size_t)or0 * D_ + col) = make_float2(acc[i][j][0], acc[i][j][1]);
                    *(float2*)(outp + (size_t)or1 * D_ + col) = make_float2(acc[i][j][2], acc[i][j][3]);
                }
            }
        }
#undef LOAD_STAGE
    }
}

// ------------------------- launch -------------------------
extern "C" void kernel_launch(void* const* d_in, const int* in_sizes, int n_in,
                              void* d_out, int out_size) {
    const float* x  = (const float*)d_in[0];
    const float* wr = (const float*)d_in[1];
    const float* wb = (const float*)d_in[2];
    const float* w1 = (const float*)d_in[3];
    const float* w2 = (const float*)d_in[4];
    float* out = (float*)d_out;

    cudaFuncSetAttribute(gemm_mma<1>, cudaFuncAttributeMaxDynamicSharedMemorySize, SMEMB);
    cudaFuncSetAttribute(gemm_mma<0>, cudaFuncAttributeMaxDynamicSharedMemorySize, SMEMB);

    router_scores_kernel<<<(B_ * L_) / 8, 256>>>(x, wr);
    rank_kernel<<<dim3(L_ / 1024, B_), 1024>>>();
    compact_kernel<<<B_, 1024>>>();

    __half *p_wb, *p_w1, *p_w2, *p_xg, *p_xu;
    int *p_sel, *p_unsel;
    cudaGetSymbolAddress((void**)&p_wb, g_wb16);
    cudaGetSymbolAddress((void**)&p_w1, g_w116);
    cudaGetSymbolAddress((void**)&p_w2, g_w216);
    cudaGetSymbolAddress((void**)&p_xg, g_xg16);
    cudaGetSymbolAddress((void**)&p_xu, g_xu16);
    cudaGetSymbolAddress((void**)&p_sel, g_selidx);
    cudaGetSymbolAddress((void**)&p_unsel, g_unselidx);

    convert16_kernel<<<(D_ * D_ / 4) / 256, 256>>>(wb, p_wb, D_ * D_ / 4);
    convert16_kernel<<<(DFF_ * D_ / 4) / 256, 256>>>(w1, p_w1, DFF_ * D_ / 4);
    convert16_kernel<<<(D_ * DFF_ / 4) / 256, 256>>>(w2, p_w2, D_ * DFF_ / 4);
    gather_convert16_kernel<<<(B_ * KCAP_  * 256) / 256, 256>>>(x, p_sel,   p_xg);
    gather_convert16_kernel<<<(B_ * UNSEL_ * 256) / 256, 256>>>(x, p_unsel, p_xu);

    // persistent GEMMs: 2 CTAs/SM x 148 SMs
    gemm_mma<1><<<296, 256, SMEMB>>>(out);   // bypass + ffn1 fused
    gemm_mma<0><<<296, 256, SMEMB>>>(out);   // ffn2 scatter
}